// round 12
// baseline (speedup 1.0000x reference)
#include <cuda_runtime.h>
#include <cuda_fp16.h>
#include <math.h>
#include <stdint.h>

// Problem constants
#define DIMX   2048
#define HEADS  16
#define HD     128
#define BATCH  4
#define SEQ    2048
#define M_TOT  8192
#define N_TOT  8192
#define K_TOT  2048

// Scan chunking
#define NCHUNK 32
#define CLEN   (SEQ / NCHUNK)        // 64
#define NCH    (BATCH * HEADS * HD)  // 8192

// Scratch
__device__ float  g_combined[(size_t)M_TOT * N_TOT];
__device__ float  g_chunkmax[(size_t)NCHUNK * NCH];
__device__ __half g_Ah[(size_t)M_TOT * K_TOT];
__device__ __half g_Bh[(size_t)N_TOT * K_TOT];

// ---------------------------------------------------------------------------
// PTX helpers
// ---------------------------------------------------------------------------
__device__ __forceinline__ uint32_t smem_u32(const void* p) {
    uint32_t a;
    asm("{ .reg .u64 t; cvta.to.shared.u64 t, %1; cvt.u32.u64 %0, t; }" : "=r"(a) : "l"(p));
    return a;
}
__device__ __forceinline__ void cp_async16(uint32_t dst, const void* src) {
    asm volatile("cp.async.cg.shared.global [%0], [%1], 16;\n" :: "r"(dst), "l"(src));
}
__device__ __forceinline__ void cp_commit() { asm volatile("cp.async.commit_group;\n"); }
template <int N> __device__ __forceinline__ void cp_wait() {
    asm volatile("cp.async.wait_group %0;\n" :: "n"(N));
}
__device__ __forceinline__ void ldmat_x4(uint32_t& r0, uint32_t& r1, uint32_t& r2, uint32_t& r3,
                                         uint32_t addr) {
    asm volatile("ldmatrix.sync.aligned.m8n8.x4.shared.b16 {%0,%1,%2,%3}, [%4];"
                 : "=r"(r0), "=r"(r1), "=r"(r2), "=r"(r3) : "r"(addr));
}
__device__ __forceinline__ void mma_f16(float& c0, float& c1, float& c2, float& c3,
                                        uint32_t a0, uint32_t a1, uint32_t a2, uint32_t a3,
                                        uint32_t b0, uint32_t b1) {
    asm volatile(
        "mma.sync.aligned.m16n8k16.row.col.f32.f16.f16.f32 "
        "{%0,%1,%2,%3}, {%4,%5,%6,%7}, {%8,%9}, {%0,%1,%2,%3};\n"
        : "+f"(c0), "+f"(c1), "+f"(c2), "+f"(c3)
        : "r"(a0), "r"(a1), "r"(a2), "r"(a3), "r"(b0), "r"(b1));
}
#define SWZ128(off) ((off) ^ (((off) >> 3) & 0x70))

// ---------------------------------------------------------------------------
// Kernel 0: convert x and W to fp16 (rn)
// ---------------------------------------------------------------------------
__global__ void cvt_kernel(const float4* __restrict__ x, const float4* __restrict__ w) {
    const size_t N8 = (size_t)M_TOT * K_TOT / 8;
    size_t i = (size_t)blockIdx.x * blockDim.x + threadIdx.x;
    if (i < N8) {
        float4 v0 = x[2 * i], v1 = x[2 * i + 1];
        __half2* o = (__half2*)(g_Ah + 8 * i);
        o[0] = __floats2half2_rn(v0.x, v0.y);
        o[1] = __floats2half2_rn(v0.z, v0.w);
        o[2] = __floats2half2_rn(v1.x, v1.y);
        o[3] = __floats2half2_rn(v1.z, v1.w);
    } else if (i < 2 * N8) {
        size_t j = i - N8;
        float4 v0 = w[2 * j], v1 = w[2 * j + 1];
        __half2* o = (__half2*)(g_Bh + 8 * j);
        o[0] = __floats2half2_rn(v0.x, v0.y);
        o[1] = __floats2half2_rn(v0.z, v0.w);
        o[2] = __floats2half2_rn(v1.x, v1.y);
        o[3] = __floats2half2_rn(v1.z, v1.w);
    }
}

// ---------------------------------------------------------------------------
// Kernel 1: FP16 mma.sync GEMM, warp tile 64x64 (4 warps, 128 threads)
// CTA tile 128x128, BK=64 halves, 3-stage cp.async ring, 96KB smem, occ 2
// ---------------------------------------------------------------------------
#define BM 128
#define BN 128
#define BK 64
#define KT (K_TOT / BK)                        // 32
#define STAGES 3
#define A_STAGE_BYTES (BM * BK * 2)            // 16384
#define B_STAGE_BYTES (BN * BK * 2)            // 16384
#define STAGE_BYTES (A_STAGE_BYTES + B_STAGE_BYTES)
#define SMEM_DYN (STAGES * STAGE_BYTES + 1024) // 99328

__global__ __launch_bounds__(128, 2)
void gemm_f16_kernel() {
    extern __shared__ char dynsmem[];

    const int tid  = threadIdx.x;
    const int warp = tid >> 5;
    const int lane = tid & 31;
    const int bm   = blockIdx.y * BM;
    const int bn   = blockIdx.x * BN;

    const uint32_t sbase = (smem_u32(dynsmem) + 1023u) & ~1023u;

    const int wm = (warp >> 1) * 64;   // warp m origin: 0/64
    const int wn = (warp & 1) * 64;    // warp n origin: 0/64

    // ldmatrix lane geometry (validated fragment map)
    const int lr   = lane & 7;
    const int gA1  = (lane >> 3) & 1;
    const int gA2  = lane >> 4;
    const int gB1  = lane >> 4;
    const int gB2  = (lane >> 3) & 1;

    uint32_t aRow[4], bRow[4];
    #pragma unroll
    for (int mf = 0; mf < 4; mf++)
        aRow[mf] = (uint32_t)(wm + mf * 16 + gA1 * 8 + lr) * 128u;
    #pragma unroll
    for (int nfp = 0; nfp < 4; nfp++)
        bRow[nfp] = (uint32_t)(wn + nfp * 16 + gB1 * 8 + lr) * 128u;

    // cp.async: 128 threads, 8 slots each for A and B per stage
    // slot i: row = (tid>>3) + i*16, chunk = tid&7 (fixed); swizzle additive in i
    const int lrow = tid >> 3;
    const int lch  = tid & 7;
    const uint32_t base_sw = SWZ128((uint32_t)(lrow * 128 + lch * 16));
    const size_t ofsA_base = (size_t)(bm + lrow) * K_TOT + lch * 8;
    const size_t ofsB_base = (size_t)(bn + lrow) * K_TOT + lch * 8;

    float acc[4][8][4];
    #pragma unroll
    for (int i = 0; i < 4; i++)
        #pragma unroll
        for (int j = 0; j < 8; j++)
            #pragma unroll
            for (int v = 0; v < 4; v++) acc[i][j][v] = 0.0f;

    auto load_stage = [&](int buf, int kt) {
        const uint32_t da = sbase + buf * STAGE_BYTES;
        const uint32_t db = da + A_STAGE_BYTES;
        const uint32_t ko = (uint32_t)(kt * BK);
        #pragma unroll
        for (int i = 0; i < 8; i++)
            cp_async16(da + base_sw + i * 2048u, g_Ah + ofsA_base + (size_t)i * 16 * K_TOT + ko);
        #pragma unroll
        for (int i = 0; i < 8; i++)
            cp_async16(db + base_sw + i * 2048u, g_Bh + ofsB_base + (size_t)i * 16 * K_TOT + ko);
        cp_commit();
    };

    load_stage(0, 0);
    load_stage(1, 1);

    int buf = 0;
    #pragma unroll 1
    for (int kt = 0; kt < KT; kt++) {
        if (kt + 1 < KT) cp_wait<1>(); else cp_wait<0>();
        __syncthreads();

        if (kt + 2 < KT) {
            int nb = buf + 2; if (nb >= STAGES) nb -= STAGES;
            load_stage(nb, kt + 2);
        }

        const uint32_t aOff = sbase + buf * STAGE_BYTES;
        const uint32_t bOff = aOff + A_STAGE_BYTES;

        #pragma unroll
        for (int ks = 0; ks < 4; ks++) {       // 4 x K=16 substeps
            const int kc = ks * 2;
            uint32_t a[4][4];
            #pragma unroll
            for (int mf = 0; mf < 4; mf++) {
                uint32_t addr = aOff + aRow[mf] + ((uint32_t)((kc + gA2) ^ lr) << 4);
                ldmat_x4(a[mf][0], a[mf][1], a[mf][2], a[mf][3], addr);
            }
            uint32_t b[4][4];
            #pragma unroll
            for (int nfp = 0; nfp < 4; nfp++) {
                uint32_t addr = bOff + bRow[nfp] + ((uint32_t)((kc + gB2) ^ lr) << 4);
                ldmat_x4(b[nfp][0], b[nfp][1], b[nfp][2], b[nfp][3], addr);
            }
            #pragma unroll
            for (int mf = 0; mf < 4; mf++)
                #pragma unroll
                for (int nfp = 0; nfp < 4; nfp++) {
                    mma_f16(acc[mf][2 * nfp][0], acc[mf][2 * nfp][1],
                            acc[mf][2 * nfp][2], acc[mf][2 * nfp][3],
                            a[mf][0], a[mf][1], a[mf][2], a[mf][3],
                            b[nfp][0], b[nfp][1]);
                    mma_f16(acc[mf][2 * nfp + 1][0], acc[mf][2 * nfp + 1][1],
                            acc[mf][2 * nfp + 1][2], acc[mf][2 * nfp + 1][3],
                            a[mf][0], a[mf][1], a[mf][2], a[mf][3],
                            b[nfp][2], b[nfp][3]);
                }
        }
        buf++; if (buf >= STAGES) buf = 0;
    }

    // Epilogue
    const int grp = lane >> 2, tig = lane & 3;
    #pragma unroll
    for (int mf = 0; mf < 4; mf++) {
        const int row = bm + wm + mf * 16 + grp;
        #pragma unroll
        for (int nf = 0; nf < 8; nf++) {
            const int col = bn + wn + nf * 8 + 2 * tig;
            *(float2*)(g_combined + (size_t)row * N_TOT + col) =
                make_float2(acc[mf][nf][0], acc[mf][nf][1]);
            *(float2*)(g_combined + (size_t)(row + 8) * N_TOT + col) =
                make_float2(acc[mf][nf][2], acc[mf][nf][3]);
        }
    }
}

// ---------------------------------------------------------------------------
// Kernel 2: per-(channel, chunk) max of c over its sequence chunk
// ---------------------------------------------------------------------------
__global__ void chunkmax_kernel() {
    const int idx = blockIdx.x * blockDim.x + threadIdx.x;
    if (idx >= NCH * NCHUNK) return;
    const int ch    = idx % NCH;
    const int chunk = idx / NCH;

    const int b    = ch / (HEADS * HD);
    const int rem  = ch % (HEADS * HD);
    const int head = rem / HD;
    const int hd   = rem % HD;

    const float* cptr = g_combined + (size_t)b * SEQ * N_TOT
                        + (size_t)2 * DIMX + (size_t)head * HD + hd;
    float m = -INFINITY;
    const int s0 = chunk * CLEN;
    for (int s = s0; s < s0 + CLEN; s++) {
        m = fmaxf(m, cptr[(size_t)s * N_TOT]);
    }
    g_chunkmax[(size_t)chunk * NCH + ch] = m;
}

// ---------------------------------------------------------------------------
// Kernel 3 (v2): coalesced reads + smem transpose + float4 coalesced writes
// block = (b, chunk, hd-half): 1024 channels (16 heads x 64 hd), 256 threads
// ---------------------------------------------------------------------------
#define SB 8                    // s-rows per smem round
#define SROW 1104               // 16 heads * 69 (padded)

__global__ __launch_bounds__(256)
void scan_out2_kernel(const float* __restrict__ alphas,
                      float* __restrict__ out,
                      long long out_size) {
    __shared__ float sm[SB * SROW];

    const int t     = threadIdx.x;
    const int bid   = blockIdx.x;
    const int cg    = bid & 1;             // hd half
    const int chunk = (bid >> 1) & (NCHUNK - 1);
    const int b     = bid >> 6;
    const int hd0   = cg * 64;

    const float a1 = alphas[0];
    const float a2 = alphas[1];
    const float a3 = alphas[2];

    // 4 channels per thread: cidx = r*256 + t -> head = cidx>>6, q = cidx&63
    int headv[4], qv[4], colv[4];
    #pragma unroll
    for (int r = 0; r < 4; r++) {
        int cidx = r * 256 + t;
        headv[r] = cidx >> 6;
        qv[r]    = cidx & 63;
        colv[r]  = headv[r] * HD + hd0 + qv[r];   // column within one projection
    }

    // carry-in from previous chunks
    float e[4] = {-INFINITY, -INFINITY, -INFINITY, -INFINITY};
    for (int j = 0; j < chunk; j++) {
        const float* cm = g_chunkmax + (size_t)j * NCH + (size_t)b * (HEADS * HD);
        #pragma unroll
        for (int r = 0; r < 4; r++) e[r] = fmaxf(e[r], cm[colv[r]]);
    }

    const int s0 = chunk * CLEN;
    const size_t rowstride = N_TOT;
    const float* base = g_combined + (size_t)(b * SEQ + s0) * rowstride;
    float* outbase = out + (size_t)(b * SEQ + s0) * DIMX + hd0 * 16;

    #pragma unroll 1
    for (int sb = 0; sb < CLEN / SB; sb++) {
        #pragma unroll 1
        for (int s2 = 0; s2 < SB; s2++) {
            const float* row = base + (size_t)(sb * SB + s2) * rowstride;
            float* smrow = sm + s2 * SROW;
            #pragma unroll
            for (int r = 0; r < 4; r++) {
                const int c = colv[r];
                const float av = row[c];
                const float bv = row[DIMX + c];
                const float cv = row[2 * DIMX + c];
                const float dv = row[3 * DIMX + c];
                e[r] = fmaxf(e[r], cv);
                const float o = bv * (av + a1 + cv + e[r]) + a2 * dv
                                + av * fmaf(a3, e[r], dv) + cv * e[r];
                smrow[headv[r] * 69 + qv[r]] = o;
            }
        }
        __syncthreads();
        // coalesced writes: thread t writes float4 at p_local = 4t of each row
        const int ph = (4 * t) & 15;       // head base of the 4 positions
        const int pq = t >> 2;             // q (same for all 4)
        #pragma unroll
        for (int s2 = 0; s2 < SB; s2++) {
            const float* smrow = sm + s2 * SROW;
            float4 v = make_float4(smrow[(ph + 0) * 69 + pq],
                                   smrow[(ph + 1) * 69 + pq],
                                   smrow[(ph + 2) * 69 + pq],
                                   smrow[(ph + 3) * 69 + pq]);
            *(float4*)(outbase + (size_t)(sb * SB + s2) * DIMX + 4 * t) = v;
        }
        __syncthreads();
    }

    // state (final chunk): same transpose path through smem
    if (chunk == NCHUNK - 1) {
        const size_t state_base = (size_t)BATCH * SEQ * DIMX;
        if (out_size >= (long long)(state_base + (size_t)BATCH * HD * HEADS)) {
            #pragma unroll
            for (int r = 0; r < 4; r++) sm[headv[r] * 69 + qv[r]] = e[r];
            __syncthreads();
            const int ph = (4 * t) & 15;
            const int pq = t >> 2;
            float4 v = make_float4(sm[(ph + 0) * 69 + pq], sm[(ph + 1) * 69 + pq],
                                   sm[(ph + 2) * 69 + pq], sm[(ph + 3) * 69 + pq]);
            *(float4*)(out + state_base + (size_t)b * (HD * HEADS) + hd0 * 16 + 4 * t) = v;
        }
    }
}

// ---------------------------------------------------------------------------
extern "C" void kernel_launch(void* const* d_in, const int* in_sizes, int n_in,
                              void* d_out, int out_size) {
    const float* x      = (const float*)d_in[0];
    const float* W      = (const float*)d_in[1];
    const float* alphas = (const float*)d_in[2];
    float* out = (float*)d_out;

    cudaFuncSetAttribute(gemm_f16_kernel,
                         cudaFuncAttributeMaxDynamicSharedMemorySize, SMEM_DYN);

    const size_t cvt_total = 2 * ((size_t)M_TOT * K_TOT / 8);
    cvt_kernel<<<(unsigned)((cvt_total + 255) / 256), 256>>>((const float4*)x, (const float4*)W);

    dim3 gemm_grid(N_TOT / BN, M_TOT / BM);   // (64, 64)
    gemm_f16_kernel<<<gemm_grid, 128, SMEM_DYN>>>();

    const int scan_threads = NCH * NCHUNK;
    chunkmax_kernel<<<(scan_threads + 255) / 256, 256>>>();

    scan_out2_kernel<<<BATCH * NCHUNK * 2, 256>>>(alphas, out, (long long)out_size);
}